// round 1
// baseline (speedup 1.0000x reference)
#include <cuda_runtime.h>
#include <cuda_bf16.h>
#include <math.h>

#define BB 2
#define SS 2048
#define DD 1024
#define HH 16
#define HDIM 64

// Scratch buffers (device globals: no allocation allowed)
__device__ float g_Q[(size_t)BB * SS * DD];        // 16 MB
__device__ float g_KV[(size_t)BB * SS * 2 * DD];   // 32 MB
__device__ float g_AO[(size_t)BB * SS * DD];       // 16 MB

// ---------------------------------------------------------------------------
// GEMM: C[M,N] = A[M,K] @ W[K,N] + bias[N]
// 128x128 tile, BK=8, 256 threads, 8x8 micro-tile
// ---------------------------------------------------------------------------
#define GBM 128
#define GBN 128
#define GBK 8

__global__ __launch_bounds__(256) void gemm_bias_kernel(
    const float* __restrict__ A, const float* __restrict__ W,
    const float* __restrict__ bias, float* __restrict__ C,
    int M, int N, int K)
{
    __shared__ float As[GBK][GBM + 4];   // [k][m], padded
    __shared__ float Bs[GBK][GBN];       // [k][n]

    const int t  = threadIdx.x;
    const int tx = t % 16;
    const int ty = t / 16;

    const int aRow0 = blockIdx.y * GBM;
    const int bCol0 = blockIdx.x * GBN;

    // load mapping
    const int a_r  = t / 2;            // 0..127
    const int a_c4 = (t % 2) * 4;      // 0 or 4
    const int b_r  = t / 32;           // 0..7
    const int b_c4 = (t % 32) * 4;     // 0..124

    const float* Aptr = A + (size_t)(aRow0 + a_r) * K + a_c4;
    const float* Wptr = W + (size_t)b_r * N + bCol0 + b_c4;

    float acc[8][8];
#pragma unroll
    for (int i = 0; i < 8; i++)
#pragma unroll
        for (int j = 0; j < 8; j++) acc[i][j] = 0.0f;

    for (int k0 = 0; k0 < K; k0 += GBK) {
        float4 av = *(const float4*)(Aptr + k0);
        float4 bv = *(const float4*)(Wptr + (size_t)k0 * N);
        As[a_c4 + 0][a_r] = av.x;
        As[a_c4 + 1][a_r] = av.y;
        As[a_c4 + 2][a_r] = av.z;
        As[a_c4 + 3][a_r] = av.w;
        *(float4*)&Bs[b_r][b_c4] = bv;
        __syncthreads();

#pragma unroll
        for (int kk = 0; kk < GBK; kk++) {
            float4 a0 = *(const float4*)&As[kk][ty * 8];
            float4 a1 = *(const float4*)&As[kk][ty * 8 + 4];
            float4 b0 = *(const float4*)&Bs[kk][tx * 8];
            float4 b1 = *(const float4*)&Bs[kk][tx * 8 + 4];
            float a[8] = {a0.x, a0.y, a0.z, a0.w, a1.x, a1.y, a1.z, a1.w};
            float b[8] = {b0.x, b0.y, b0.z, b0.w, b1.x, b1.y, b1.z, b1.w};
#pragma unroll
            for (int i = 0; i < 8; i++)
#pragma unroll
                for (int j = 0; j < 8; j++)
                    acc[i][j] = fmaf(a[i], b[j], acc[i][j]);
        }
        __syncthreads();
    }

    // epilogue: add bias, write float4
    const int col0 = bCol0 + tx * 8;
    float4 bi0 = *(const float4*)&bias[col0];
    float4 bi1 = *(const float4*)&bias[col0 + 4];
#pragma unroll
    for (int i = 0; i < 8; i++) {
        const size_t row = (size_t)(aRow0 + ty * 8 + i);
        float4 v0 = make_float4(acc[i][0] + bi0.x, acc[i][1] + bi0.y,
                                acc[i][2] + bi0.z, acc[i][3] + bi0.w);
        float4 v1 = make_float4(acc[i][4] + bi1.x, acc[i][5] + bi1.y,
                                acc[i][6] + bi1.z, acc[i][7] + bi1.w);
        *(float4*)&C[row * N + col0]     = v0;
        *(float4*)&C[row * N + col0 + 4] = v1;
    }
}

// ---------------------------------------------------------------------------
// Flash-style causal attention.
// Grid: (S/64, H, B). Block: 256 threads.
// Each block: 64 query rows of one (b,h). Tiles of 64 keys.
// smem: Qsh[d][q] pitch 65, Ksh[d][k] pitch 65 (reused as Ps[k][q]),
//       Vs[k][d] pitch 64.
// ---------------------------------------------------------------------------
#define ATTN_SMEM ((65 * 64 * 2 + 64 * 64) * 4)

__global__ __launch_bounds__(256) void attn_kernel(
    const float* __restrict__ Q, const float* __restrict__ KV,
    float* __restrict__ O)
{
    extern __shared__ float sm[];
    float* Qsh = sm;                 // [64 d][65]
    float* Ksh = sm + 64 * 65;       // [64 d][65]  -> later Ps[64 k][65]
    float* Vs  = sm + 2 * 64 * 65;   // [64 k][64]

    const int q0 = blockIdx.x * 64;
    const int h  = blockIdx.y;
    const int b  = blockIdx.z;

    const int t  = threadIdx.x;
    const int tx = t % 16;
    const int ty = t / 16;
    const int lr = t % 64;   // dim index for loads
    const int lq = t / 64;   // 0..3

    const float* Qb = Q  + ((size_t)b * SS + q0) * DD + h * HDIM;
    const float* Kb = KV + (size_t)b * SS * 2 * DD + h * HDIM;
    const float* Vb = Kb + DD;

    // load Q tile transposed: Qsh[d][q]
    for (int qq = lq; qq < 64; qq += 4)
        Qsh[lr * 65 + qq] = Qb[(size_t)qq * DD + lr];

    float m_i[4], l_i[4], o[4][4];
#pragma unroll
    for (int i = 0; i < 4; i++) {
        m_i[i] = -1e30f;
        l_i[i] = 0.0f;
#pragma unroll
        for (int j = 0; j < 4; j++) o[i][j] = 0.0f;
    }

    const int ktmax = q0 / 64;
    const float scale = 0.125f; // 1/sqrt(64)

    for (int kt = 0; kt <= ktmax; kt++) {
        __syncthreads();  // previous iter readers done (also covers Qsh load on kt=0)

        // load K,V tiles (K transposed to [d][k], V as [k][d])
        const float* Kt = Kb + (size_t)(kt * 64) * 2 * DD;
        const float* Vt = Vb + (size_t)(kt * 64) * 2 * DD;
        for (int kk = lq; kk < 64; kk += 4) {
            Ksh[lr * 65 + kk]  = Kt[(size_t)kk * 2 * DD + lr];
            Vs[kk * 64 + lr]   = Vt[(size_t)kk * 2 * DD + lr];
        }
        __syncthreads();

        // scores: s[q=ty*4+i][k=tx*4+j] = sum_d Q[d][q] * K[d][k]
        float s[4][4];
#pragma unroll
        for (int i = 0; i < 4; i++)
#pragma unroll
            for (int j = 0; j < 4; j++) s[i][j] = 0.0f;

        for (int d = 0; d < 64; d++) {
            float a[4], bb[4];
#pragma unroll
            for (int i = 0; i < 4; i++) a[i]  = Qsh[d * 65 + ty * 4 + i];
#pragma unroll
            for (int j = 0; j < 4; j++) bb[j] = Ksh[d * 65 + tx * 4 + j];
#pragma unroll
            for (int i = 0; i < 4; i++)
#pragma unroll
                for (int j = 0; j < 4; j++)
                    s[i][j] = fmaf(a[i], bb[j], s[i][j]);
        }

        // scale + causal mask
#pragma unroll
        for (int i = 0; i < 4; i++) {
            const int qg = q0 + ty * 4 + i;
#pragma unroll
            for (int j = 0; j < 4; j++) {
                const int kg = kt * 64 + tx * 4 + j;
                s[i][j] = (kg <= qg) ? s[i][j] * scale : -1e30f;
            }
        }

        // per-row online softmax (rows owned by a 16-lane half-warp)
        float p[4][4];
        float corr[4];
#pragma unroll
        for (int i = 0; i < 4; i++) {
            float rmax = fmaxf(fmaxf(s[i][0], s[i][1]), fmaxf(s[i][2], s[i][3]));
#pragma unroll
            for (int off = 8; off > 0; off >>= 1)
                rmax = fmaxf(rmax, __shfl_xor_sync(0xffffffffu, rmax, off));
            float mn = fmaxf(m_i[i], rmax);
            corr[i] = __expf(m_i[i] - mn);
            float rsum = 0.0f;
#pragma unroll
            for (int j = 0; j < 4; j++) {
                p[i][j] = __expf(s[i][j] - mn);
                rsum += p[i][j];
            }
#pragma unroll
            for (int off = 8; off > 0; off >>= 1)
                rsum += __shfl_xor_sync(0xffffffffu, rsum, off);
            l_i[i] = l_i[i] * corr[i] + rsum;
            m_i[i] = mn;
#pragma unroll
            for (int j = 0; j < 4; j++) o[i][j] *= corr[i];
        }

        __syncthreads();  // everyone done reading Ksh before overwrite with P

        // write P to shared as Ps[k][q] (reusing Ksh storage, pitch 65)
#pragma unroll
        for (int i = 0; i < 4; i++)
#pragma unroll
            for (int j = 0; j < 4; j++)
                Ksh[(tx * 4 + j) * 65 + (ty * 4 + i)] = p[i][j];
        __syncthreads();

        // o[q][d] += P[q][k] * V[k][d]
        for (int kk = 0; kk < 64; kk++) {
            float pf[4], vf[4];
#pragma unroll
            for (int i = 0; i < 4; i++) pf[i] = Ksh[kk * 65 + ty * 4 + i];
#pragma unroll
            for (int j = 0; j < 4; j++) vf[j] = Vs[kk * 64 + tx * 4 + j];
#pragma unroll
            for (int i = 0; i < 4; i++)
#pragma unroll
                for (int j = 0; j < 4; j++)
                    o[i][j] = fmaf(pf[i], vf[j], o[i][j]);
        }
    }

    // normalize + write merged-head output O[b][q][h*64+d]
#pragma unroll
    for (int i = 0; i < 4; i++) {
        const float inv_l = 1.0f / l_i[i];
        const size_t row = ((size_t)b * SS + q0 + ty * 4 + i) * DD + h * HDIM + tx * 4;
#pragma unroll
        for (int j = 0; j < 4; j++)
            O[row + j] = o[i][j] * inv_l;
    }
}

// ---------------------------------------------------------------------------
// Launch
// ---------------------------------------------------------------------------
extern "C" void kernel_launch(void* const* d_in, const int* in_sizes, int n_in,
                              void* d_out, int out_size)
{
    const float* qf  = (const float*)d_in[0];
    const float* kvf = (const float*)d_in[1];
    // d_in[2] = mask: deterministically causal tril -> handled analytically
    const float* Wq  = (const float*)d_in[3];
    const float* bq  = (const float*)d_in[4];
    const float* Wkv = (const float*)d_in[5];
    const float* bkv = (const float*)d_in[6];
    const float* Wp  = (const float*)d_in[7];
    const float* bp  = (const float*)d_in[8];
    float* out = (float*)d_out;

    float *pQ, *pKV, *pAO;
    cudaGetSymbolAddress((void**)&pQ,  g_Q);
    cudaGetSymbolAddress((void**)&pKV, g_KV);
    cudaGetSymbolAddress((void**)&pAO, g_AO);

    const int M = BB * SS;  // 4096

    // 1) Q projection: (4096 x 1024) = qf @ Wq + bq
    gemm_bias_kernel<<<dim3(DD / GBN, M / GBM), 256>>>(qf, Wq, bq, pQ, M, DD, DD);

    // 2) KV projection: (4096 x 2048) = kvf @ Wkv + bkv
    gemm_bias_kernel<<<dim3(2 * DD / GBN, M / GBM), 256>>>(kvf, Wkv, bkv, pKV, M, 2 * DD, DD);

    // 3) causal attention
    cudaFuncSetAttribute(attn_kernel, cudaFuncAttributeMaxDynamicSharedMemorySize, ATTN_SMEM);
    attn_kernel<<<dim3(SS / 64, HH, BB), 256, ATTN_SMEM>>>(pQ, pKV, pAO);

    // 4) output projection into d_out
    gemm_bias_kernel<<<dim3(DD / GBN, M / GBM), 256>>>(pAO, Wp, bp, out, M, DD, DD);
}

// round 2
// speedup vs baseline: 2.0896x; 2.0896x over previous
#include <cuda_runtime.h>
#include <cuda_bf16.h>
#include <math.h>
#include <stdint.h>

#define BB 2
#define SS 2048
#define DD 1024
#define HH 16
#define HDIM 64

// Scratch buffers (device globals: no allocation allowed)
__device__ float g_Q[(size_t)BB * SS * DD];        // 16 MB
__device__ float g_KV[(size_t)BB * SS * 2 * DD];   // 32 MB
__device__ float g_AO[(size_t)BB * SS * DD];       // 16 MB

// ---------------------------------------------------------------------------
// helpers
// ---------------------------------------------------------------------------
__device__ __forceinline__ uint32_t f2tf32(float f) {
    uint32_t u;
    asm("cvt.rna.tf32.f32 %0, %1;" : "=r"(u) : "f"(f));
    return u;
}

__device__ __forceinline__ void mma_tf32(float c[4], const uint32_t a[4], const uint32_t b[2]) {
    asm("mma.sync.aligned.m16n8k8.row.col.f32.tf32.tf32.f32 "
        "{%0,%1,%2,%3},{%4,%5,%6,%7},{%8,%9},{%0,%1,%2,%3};"
        : "+f"(c[0]), "+f"(c[1]), "+f"(c[2]), "+f"(c[3])
        : "r"(a[0]), "r"(a[1]), "r"(a[2]), "r"(a[3]), "r"(b[0]), "r"(b[1]));
}

// ---------------------------------------------------------------------------
// TF32 tensor-core GEMM: C[M,N] = A[M,K] @ W[K,N] + bias[N]
// 128x128 tile, BK=16, 256 threads (8 warps), warp tile 64x32 (4x4 frags)
// ---------------------------------------------------------------------------
#define AP 20    // As pitch: (20*m + k) % 32 distinct for m in 0..7, k in 0..3
#define BP 136   // Bs pitch: 136 % 32 == 8 -> (8*k + n) % 32 distinct

__global__ __launch_bounds__(256) void gemm_tf32_kernel(
    const float* __restrict__ A, const float* __restrict__ W,
    const float* __restrict__ bias, float* __restrict__ C,
    int M, int N, int K)
{
    __shared__ uint32_t As[128][AP];
    __shared__ uint32_t Bs[16][BP];

    const int t    = threadIdx.x;
    const int lane = t & 31;
    const int wid  = t >> 5;
    const int gid  = lane >> 2;
    const int tig  = lane & 3;
    const int wm   = wid >> 2;   // 0..1
    const int wn   = wid & 3;    // 0..3

    const int row0 = blockIdx.y * 128;
    const int col0 = blockIdx.x * 128;

    // loader mapping
    const int ar = t >> 2;          // 0..63 (also +64)
    const int ac = (t & 3) * 4;     // 0,4,8,12
    const int br = t >> 5;          // 0..7 (also +8)
    const int bc = (t & 31) * 4;    // 0..124

    const float* Ap0 = A + (size_t)(row0 + ar) * K + ac;
    const float* Ap1 = Ap0 + (size_t)64 * K;
    const float* Wp0 = W + (size_t)br * N + col0 + bc;
    const float* Wp1 = Wp0 + (size_t)8 * N;

    float acc[4][4][4];
#pragma unroll
    for (int mf = 0; mf < 4; mf++)
#pragma unroll
        for (int nf = 0; nf < 4; nf++)
#pragma unroll
            for (int r = 0; r < 4; r++) acc[mf][nf][r] = 0.0f;

    float4 a0v = *(const float4*)Ap0;
    float4 a1v = *(const float4*)Ap1;
    float4 b0v = *(const float4*)Wp0;
    float4 b1v = *(const float4*)Wp1;

    for (int k0 = 0; k0 < K; k0 += 16) {
        // store current tile to smem (tf32)
        As[ar][ac + 0]      = f2tf32(a0v.x);
        As[ar][ac + 1]      = f2tf32(a0v.y);
        As[ar][ac + 2]      = f2tf32(a0v.z);
        As[ar][ac + 3]      = f2tf32(a0v.w);
        As[ar + 64][ac + 0] = f2tf32(a1v.x);
        As[ar + 64][ac + 1] = f2tf32(a1v.y);
        As[ar + 64][ac + 2] = f2tf32(a1v.z);
        As[ar + 64][ac + 3] = f2tf32(a1v.w);
        Bs[br][bc + 0]      = f2tf32(b0v.x);
        Bs[br][bc + 1]      = f2tf32(b0v.y);
        Bs[br][bc + 2]      = f2tf32(b0v.z);
        Bs[br][bc + 3]      = f2tf32(b0v.w);
        Bs[br + 8][bc + 0]  = f2tf32(b1v.x);
        Bs[br + 8][bc + 1]  = f2tf32(b1v.y);
        Bs[br + 8][bc + 2]  = f2tf32(b1v.z);
        Bs[br + 8][bc + 3]  = f2tf32(b1v.w);
        __syncthreads();

        // prefetch next tile (overlaps with mma below)
        if (k0 + 16 < K) {
            a0v = *(const float4*)(Ap0 + k0 + 16);
            a1v = *(const float4*)(Ap1 + k0 + 16);
            b0v = *(const float4*)(Wp0 + (size_t)(k0 + 16) * N);
            b1v = *(const float4*)(Wp1 + (size_t)(k0 + 16) * N);
        }

#pragma unroll
        for (int ks = 0; ks < 2; ks++) {
            const int kb = ks * 8;
            uint32_t af[4][4], bf[4][2];
#pragma unroll
            for (int mf = 0; mf < 4; mf++) {
                const int r = wm * 64 + mf * 16 + gid;
                af[mf][0] = As[r][kb + tig];
                af[mf][1] = As[r + 8][kb + tig];
                af[mf][2] = As[r][kb + tig + 4];
                af[mf][3] = As[r + 8][kb + tig + 4];
            }
#pragma unroll
            for (int nf = 0; nf < 4; nf++) {
                const int c = wn * 32 + nf * 8 + gid;
                bf[nf][0] = Bs[kb + tig][c];
                bf[nf][1] = Bs[kb + tig + 4][c];
            }
#pragma unroll
            for (int mf = 0; mf < 4; mf++)
#pragma unroll
                for (int nf = 0; nf < 4; nf++)
                    mma_tf32(acc[mf][nf], af[mf], bf[nf]);
        }
        __syncthreads();
    }

    // epilogue: bias + float2 stores
#pragma unroll
    for (int nf = 0; nf < 4; nf++) {
        const int c = col0 + wn * 32 + nf * 8 + 2 * tig;
        const float2 bb = *(const float2*)&bias[c];
#pragma unroll
        for (int mf = 0; mf < 4; mf++) {
            const int r = row0 + wm * 64 + mf * 16 + gid;
            float2 v0 = make_float2(acc[mf][nf][0] + bb.x, acc[mf][nf][1] + bb.y);
            float2 v1 = make_float2(acc[mf][nf][2] + bb.x, acc[mf][nf][3] + bb.y);
            *(float2*)&C[(size_t)r * N + c]       = v0;
            *(float2*)&C[(size_t)(r + 8) * N + c] = v1;
        }
    }
}

// ---------------------------------------------------------------------------
// Flash-style causal attention with tf32 mma.
// Grid: (S/64, H, B). Block: 128 threads (4 warps), each warp owns 16 q rows.
// ---------------------------------------------------------------------------
#define QP 68   // Q/P pitch: (4*gid + tig) distinct -> conflict-free A frags
#define KP 72   // K/V pitch: (8*n + k) distinct   -> conflict-free B frags
#define ATTN_SMEM_WORDS (64 * (2 * QP + 2 * KP))
#define ATTN_SMEM_BYTES (ATTN_SMEM_WORDS * 4)

__global__ __launch_bounds__(128) void attn_tf32_kernel(
    const float* __restrict__ Q, const float* __restrict__ KV,
    float* __restrict__ O)
{
    extern __shared__ uint32_t sm[];
    uint32_t* Qs = sm;                    // [64][QP]
    uint32_t* Ps = Qs + 64 * QP;          // [64][QP]
    uint32_t* Ks = Ps + 64 * QP;          // [64][KP]
    uint32_t* Vs = Ks + 64 * KP;          // [64][KP]

    const int t    = threadIdx.x;
    const int lane = t & 31;
    const int wid  = t >> 5;   // 0..3
    const int gid  = lane >> 2;
    const int tig  = lane & 3;

    const int q0 = blockIdx.x * 64;
    const int h  = blockIdx.y;
    const int b  = blockIdx.z;

    // loaders: row = t/2 (0..63), half = t&1 covers 32 cols
    const int lrow = t >> 1;
    const int lcol0 = (t & 1) * 32;

    const float* Qb = Q  + ((size_t)b * SS + q0 + lrow) * DD + h * HDIM;
    const float* Kb = KV + (size_t)b * SS * 2 * DD + h * HDIM;
    const float* Vb = Kb + DD;

    // load Q tile (scale folded in)
#pragma unroll
    for (int i = 0; i < 8; i++) {
        const int c = lcol0 + i * 4;
        float4 v = *(const float4*)(Qb + c);
        Qs[lrow * QP + c + 0] = f2tf32(v.x * 0.125f);
        Qs[lrow * QP + c + 1] = f2tf32(v.y * 0.125f);
        Qs[lrow * QP + c + 2] = f2tf32(v.z * 0.125f);
        Qs[lrow * QP + c + 3] = f2tf32(v.w * 0.125f);
    }

    float m_i[2], l_i[2];
    float of[8][4];
    m_i[0] = m_i[1] = -1e30f;
    l_i[0] = l_i[1] = 0.0f;
#pragma unroll
    for (int nf = 0; nf < 8; nf++)
#pragma unroll
        for (int r = 0; r < 4; r++) of[nf][r] = 0.0f;

    const int ktdiag = blockIdx.x;
    const int qrow = wid * 16 + gid;   // local q row (and +8)

    for (int kt = 0; kt <= ktdiag; kt++) {
        __syncthreads();   // prev iter readers done (and Q visible after next sync)

        // load K,V tiles [kk][d]
        const float* Kt = Kb + (size_t)(kt * 64 + lrow) * 2 * DD;
        const float* Vt = Vb + (size_t)(kt * 64 + lrow) * 2 * DD;
#pragma unroll
        for (int i = 0; i < 8; i++) {
            const int c = lcol0 + i * 4;
            float4 kv4 = *(const float4*)(Kt + c);
            float4 vv4 = *(const float4*)(Vt + c);
            Ks[lrow * KP + c + 0] = f2tf32(kv4.x);
            Ks[lrow * KP + c + 1] = f2tf32(kv4.y);
            Ks[lrow * KP + c + 2] = f2tf32(kv4.z);
            Ks[lrow * KP + c + 3] = f2tf32(kv4.w);
            Vs[lrow * KP + c + 0] = f2tf32(vv4.x);
            Vs[lrow * KP + c + 1] = f2tf32(vv4.y);
            Vs[lrow * KP + c + 2] = f2tf32(vv4.z);
            Vs[lrow * KP + c + 3] = f2tf32(vv4.w);
        }
        __syncthreads();

        // S = Q @ K^T  (k-dim = d)
        float sf[8][4];
#pragma unroll
        for (int nf = 0; nf < 8; nf++)
#pragma unroll
            for (int r = 0; r < 4; r++) sf[nf][r] = 0.0f;

#pragma unroll
        for (int ks = 0; ks < 8; ks++) {
            const int kb = ks * 8;
            uint32_t af[4];
            af[0] = Qs[(qrow)     * QP + kb + tig];
            af[1] = Qs[(qrow + 8) * QP + kb + tig];
            af[2] = Qs[(qrow)     * QP + kb + tig + 4];
            af[3] = Qs[(qrow + 8) * QP + kb + tig + 4];
#pragma unroll
            for (int nf = 0; nf < 8; nf++) {
                uint32_t bf[2];
                bf[0] = Ks[(nf * 8 + gid) * KP + kb + tig];
                bf[1] = Ks[(nf * 8 + gid) * KP + kb + tig + 4];
                mma_tf32(sf[nf], af, bf);
            }
        }

        // causal mask (diagonal tile only)
        if (kt == ktdiag) {
            const int rg0 = q0 + qrow;
#pragma unroll
            for (int nf = 0; nf < 8; nf++) {
                const int cg = kt * 64 + nf * 8 + 2 * tig;
                if (cg     > rg0)     sf[nf][0] = -1e30f;
                if (cg + 1 > rg0)     sf[nf][1] = -1e30f;
                if (cg     > rg0 + 8) sf[nf][2] = -1e30f;
                if (cg + 1 > rg0 + 8) sf[nf][3] = -1e30f;
            }
        }

        // online softmax per row (rows gid and gid+8; quad = 4 lanes share row)
#pragma unroll
        for (int r = 0; r < 2; r++) {
            float vmax = -1e30f;
#pragma unroll
            for (int nf = 0; nf < 8; nf++)
                vmax = fmaxf(vmax, fmaxf(sf[nf][2 * r], sf[nf][2 * r + 1]));
            vmax = fmaxf(vmax, __shfl_xor_sync(0xffffffffu, vmax, 1));
            vmax = fmaxf(vmax, __shfl_xor_sync(0xffffffffu, vmax, 2));
            const float mn = fmaxf(m_i[r], vmax);
            const float corr = __expf(m_i[r] - mn);
            float rsum = 0.0f;
#pragma unroll
            for (int nf = 0; nf < 8; nf++) {
                float p0 = __expf(sf[nf][2 * r]     - mn);
                float p1 = __expf(sf[nf][2 * r + 1] - mn);
                sf[nf][2 * r]     = p0;
                sf[nf][2 * r + 1] = p1;
                rsum += p0 + p1;
            }
            rsum += __shfl_xor_sync(0xffffffffu, rsum, 1);
            rsum += __shfl_xor_sync(0xffffffffu, rsum, 2);
            l_i[r] = l_i[r] * corr + rsum;
            m_i[r] = mn;
#pragma unroll
            for (int nf = 0; nf < 8; nf++) {
                of[nf][2 * r]     *= corr;
                of[nf][2 * r + 1] *= corr;
            }
        }

        // stage P (rows are warp-private -> only syncwarp needed)
#pragma unroll
        for (int nf = 0; nf < 8; nf++) {
            const int cc = nf * 8 + 2 * tig;
            uint2 p01 = make_uint2(f2tf32(sf[nf][0]), f2tf32(sf[nf][1]));
            uint2 p23 = make_uint2(f2tf32(sf[nf][2]), f2tf32(sf[nf][3]));
            *(uint2*)&Ps[(qrow)     * QP + cc] = p01;
            *(uint2*)&Ps[(qrow + 8) * QP + cc] = p23;
        }
        __syncwarp();

        // O += P @ V  (k-dim = kk)
#pragma unroll
        for (int ks = 0; ks < 8; ks++) {
            const int kb = ks * 8;
            uint32_t af[4];
            af[0] = Ps[(qrow)     * QP + kb + tig];
            af[1] = Ps[(qrow + 8) * QP + kb + tig];
            af[2] = Ps[(qrow)     * QP + kb + tig + 4];
            af[3] = Ps[(qrow + 8) * QP + kb + tig + 4];
#pragma unroll
            for (int nf = 0; nf < 8; nf++) {
                uint32_t bf[2];
                bf[0] = Vs[(kb + tig)     * KP + nf * 8 + gid];
                bf[1] = Vs[(kb + tig + 4) * KP + nf * 8 + gid];
                mma_tf32(of[nf], af, bf);
            }
        }
    }

    // epilogue: normalize + merged-head write O[b][q][h*64+d]
    const float inv0 = 1.0f / l_i[0];
    const float inv1 = 1.0f / l_i[1];
    const size_t base0 = ((size_t)b * SS + q0 + qrow)     * DD + h * HDIM;
    const size_t base1 = ((size_t)b * SS + q0 + qrow + 8) * DD + h * HDIM;
#pragma unroll
    for (int nf = 0; nf < 8; nf++) {
        const int cc = nf * 8 + 2 * tig;
        *(float2*)&O[base0 + cc] = make_float2(of[nf][0] * inv0, of[nf][1] * inv0);
        *(float2*)&O[base1 + cc] = make_float2(of[nf][2] * inv1, of[nf][3] * inv1);
    }
}

// ---------------------------------------------------------------------------
// Launch
// ---------------------------------------------------------------------------
extern "C" void kernel_launch(void* const* d_in, const int* in_sizes, int n_in,
                              void* d_out, int out_size)
{
    const float* qf  = (const float*)d_in[0];
    const float* kvf = (const float*)d_in[1];
    // d_in[2] = mask: deterministically causal tril -> handled analytically
    const float* Wq  = (const float*)d_in[3];
    const float* bq  = (const float*)d_in[4];
    const float* Wkv = (const float*)d_in[5];
    const float* bkv = (const float*)d_in[6];
    const float* Wp  = (const float*)d_in[7];
    const float* bp  = (const float*)d_in[8];
    float* out = (float*)d_out;

    float *pQ, *pKV, *pAO;
    cudaGetSymbolAddress((void**)&pQ,  g_Q);
    cudaGetSymbolAddress((void**)&pKV, g_KV);
    cudaGetSymbolAddress((void**)&pAO, g_AO);

    const int M = BB * SS;  // 4096

    // 1) Q projection: (4096 x 1024)
    gemm_tf32_kernel<<<dim3(DD / 128, M / 128), 256>>>(qf, Wq, bq, pQ, M, DD, DD);

    // 2) KV projection: (4096 x 2048)
    gemm_tf32_kernel<<<dim3(2 * DD / 128, M / 128), 256>>>(kvf, Wkv, bkv, pKV, M, 2 * DD, DD);

    // 3) causal attention (tf32 mma)
    cudaFuncSetAttribute(attn_tf32_kernel, cudaFuncAttributeMaxDynamicSharedMemorySize, ATTN_SMEM_BYTES);
    attn_tf32_kernel<<<dim3(SS / 64, HH, BB), 128, ATTN_SMEM_BYTES>>>(pQ, pKV, pAO);

    // 4) output projection into d_out
    gemm_tf32_kernel<<<dim3(DD / 128, M / 128), 256>>>(pAO, Wp, bp, out, M, DD, DD);
}

// round 3
// speedup vs baseline: 2.7007x; 1.2925x over previous
#include <cuda_runtime.h>
#include <cuda_bf16.h>
#include <math.h>
#include <stdint.h>

#define BB 2
#define SS 2048
#define DD 1024
#define HH 16
#define HDIM 64

// Scratch buffers (device globals: no allocation allowed)
__device__ float g_Q[(size_t)BB * SS * DD];        // 16 MB
__device__ float g_KV[(size_t)BB * SS * 2 * DD];   // 32 MB
__device__ float g_AO[(size_t)BB * SS * DD];       // 16 MB

// ---------------------------------------------------------------------------
// helpers
// ---------------------------------------------------------------------------
__device__ __forceinline__ uint32_t f2tf32(float f) {
    uint32_t u;
    asm("cvt.rna.tf32.f32 %0, %1;" : "=r"(u) : "f"(f));
    return u;
}

__device__ __forceinline__ uint4 cvt4(float4 v) {
    uint4 r;
    r.x = f2tf32(v.x); r.y = f2tf32(v.y); r.z = f2tf32(v.z); r.w = f2tf32(v.w);
    return r;
}

__device__ __forceinline__ void mma_tf32(float c[4], const uint32_t a[4], const uint32_t b[2]) {
    asm("mma.sync.aligned.m16n8k8.row.col.f32.tf32.tf32.f32 "
        "{%0,%1,%2,%3},{%4,%5,%6,%7},{%8,%9},{%0,%1,%2,%3};"
        : "+f"(c[0]), "+f"(c[1]), "+f"(c[2]), "+f"(c[3])
        : "r"(a[0]), "r"(a[1]), "r"(a[2]), "r"(a[3]), "r"(b[0]), "r"(b[1]));
}

// ---------------------------------------------------------------------------
// TF32 tensor-core GEMM: C[M,N] = A[M,K] @ W[K,N] + bias[N]
// 128x128 tile, BK=32, 256 threads (8 warps), warp tile 64x32 (4x4 frags)
// ---------------------------------------------------------------------------
#define AP 36    // As pitch: (36*r + k) % 32 -> (4*gid + tig) distinct
#define BP 136   // Bs pitch: 136 % 32 == 8 -> (8*k + n) distinct

__global__ __launch_bounds__(256) void gemm_tf32_kernel(
    const float* __restrict__ A, const float* __restrict__ W,
    const float* __restrict__ bias, float* __restrict__ C,
    int M, int N, int K)
{
    __shared__ uint32_t As[128][AP];   // 18432 B
    __shared__ uint32_t Bs[32][BP];    // 17408 B

    const int t    = threadIdx.x;
    const int lane = t & 31;
    const int wid  = t >> 5;
    const int gid  = lane >> 2;
    const int tig  = lane & 3;
    const int wm   = wid >> 2;   // 0..1
    const int wn   = wid & 3;    // 0..3

    const int row0 = blockIdx.y * 128;
    const int col0 = blockIdx.x * 128;

    // loader mapping (BK = 32)
    const int ar  = t >> 1;          // 0..127
    const int ac0 = (t & 1) * 16;    // 0 or 16 (4x float4 each)
    const int br0 = t >> 5;          // 0..7 (rows br0, +8, +16, +24)
    const int bc  = (t & 31) * 4;    // 0..124

    const float* Ap = A + (size_t)(row0 + ar) * K + ac0;
    const float* Wp = W + (size_t)br0 * N + col0 + bc;

    float acc[4][4][4];
#pragma unroll
    for (int mf = 0; mf < 4; mf++)
#pragma unroll
        for (int nf = 0; nf < 4; nf++)
#pragma unroll
            for (int r = 0; r < 4; r++) acc[mf][nf][r] = 0.0f;

    float4 apre[4], bpre[4];
#pragma unroll
    for (int i = 0; i < 4; i++) apre[i] = *(const float4*)(Ap + i * 4);
#pragma unroll
    for (int i = 0; i < 4; i++) bpre[i] = *(const float4*)(Wp + (size_t)(8 * i) * N);

    for (int k0 = 0; k0 < K; k0 += 32) {
        // store current tile to smem (tf32, STS.128)
#pragma unroll
        for (int i = 0; i < 4; i++) {
            *(uint4*)&As[ar][ac0 + 4 * i]  = cvt4(apre[i]);
            *(uint4*)&Bs[br0 + 8 * i][bc]  = cvt4(bpre[i]);
        }
        __syncthreads();

        // prefetch next tile (overlaps with mma below)
        if (k0 + 32 < K) {
#pragma unroll
            for (int i = 0; i < 4; i++)
                apre[i] = *(const float4*)(Ap + k0 + 32 + i * 4);
#pragma unroll
            for (int i = 0; i < 4; i++)
                bpre[i] = *(const float4*)(Wp + (size_t)(k0 + 32 + 8 * i) * N);
        }

#pragma unroll
        for (int ks = 0; ks < 4; ks++) {
            const int kb = ks * 8;
            uint32_t af[4][4], bf[4][2];
#pragma unroll
            for (int mf = 0; mf < 4; mf++) {
                const int r = wm * 64 + mf * 16 + gid;
                af[mf][0] = As[r][kb + tig];
                af[mf][1] = As[r + 8][kb + tig];
                af[mf][2] = As[r][kb + tig + 4];
                af[mf][3] = As[r + 8][kb + tig + 4];
            }
#pragma unroll
            for (int nf = 0; nf < 4; nf++) {
                const int c = wn * 32 + nf * 8 + gid;
                bf[nf][0] = Bs[kb + tig][c];
                bf[nf][1] = Bs[kb + tig + 4][c];
            }
#pragma unroll
            for (int mf = 0; mf < 4; mf++)
#pragma unroll
                for (int nf = 0; nf < 4; nf++)
                    mma_tf32(acc[mf][nf], af[mf], bf[nf]);
        }
        __syncthreads();
    }

    // epilogue: bias + float2 stores
#pragma unroll
    for (int nf = 0; nf < 4; nf++) {
        const int c = col0 + wn * 32 + nf * 8 + 2 * tig;
        const float2 bb = *(const float2*)&bias[c];
#pragma unroll
        for (int mf = 0; mf < 4; mf++) {
            const int r = row0 + wm * 64 + mf * 16 + gid;
            float2 v0 = make_float2(acc[mf][nf][0] + bb.x, acc[mf][nf][1] + bb.y);
            float2 v1 = make_float2(acc[mf][nf][2] + bb.x, acc[mf][nf][3] + bb.y);
            *(float2*)&C[(size_t)r * N + c]       = v0;
            *(float2*)&C[(size_t)(r + 8) * N + c] = v1;
        }
    }
}

// ---------------------------------------------------------------------------
// Flash-style causal attention, tf32 mma, double-buffered K/V pipeline.
// Grid: (S/128, H, B). Block: 256 threads (8 warps), q-tile 128, k-tile 64.
// ---------------------------------------------------------------------------
#define QP 68   // Q/P pitch: conflict-free A-frag reads
#define KP 72   // K/V pitch: conflict-free B-frag reads
#define ATTN_SMEM_WORDS (128 * QP * 2 + 2 * 64 * KP * 2)
#define ATTN_SMEM_BYTES (ATTN_SMEM_WORDS * 4)

__global__ __launch_bounds__(256) void attn_tf32_kernel(
    const float* __restrict__ Q, const float* __restrict__ KV,
    float* __restrict__ O)
{
    extern __shared__ uint32_t sm[];
    uint32_t* Qs = sm;                     // [128][QP]
    uint32_t* Ps = Qs + 128 * QP;          // [128][QP]
    uint32_t* Ks = Ps + 128 * QP;          // [2][64][KP]
    uint32_t* Vs = Ks + 2 * 64 * KP;       // [2][64][KP]

    const int t    = threadIdx.x;
    const int lane = t & 31;
    const int wid  = t >> 5;   // 0..7
    const int gid  = lane >> 2;
    const int tig  = lane & 3;

    // reverse bx so heaviest (most k-tiles) blocks launch first
    const int bxr = gridDim.x - 1 - blockIdx.x;
    const int q0 = bxr * 128;
    const int h  = blockIdx.y;
    const int b  = blockIdx.z;

    // loader mappings
    const int qlrow = t >> 1;          // 0..127
    const int qlc0  = (t & 1) * 32;    // 8x float4
    const int klrow = t >> 2;          // 0..63
    const int klc0  = (t & 3) * 16;    // 4x float4

    const float* Qb = Q  + ((size_t)b * SS + q0 + qlrow) * DD + h * HDIM + qlc0;
    const float* Kb = KV + (size_t)b * SS * 2 * DD + h * HDIM + klc0;
    const float* Vb = Kb + DD;

    // load Q tile (scale folded in)
#pragma unroll
    for (int i = 0; i < 8; i++) {
        float4 v = *(const float4*)(Qb + i * 4);
        v.x *= 0.125f; v.y *= 0.125f; v.z *= 0.125f; v.w *= 0.125f;
        *(uint4*)&Qs[qlrow * QP + qlc0 + 4 * i] = cvt4(v);
    }

    // prologue: K/V tile 0 into buffer 0
    float4 kpre[4], vpre[4];
    {
        const float* Kt = Kb + (size_t)klrow * 2 * DD;
        const float* Vt = Vb + (size_t)klrow * 2 * DD;
#pragma unroll
        for (int i = 0; i < 4; i++) {
            kpre[i] = *(const float4*)(Kt + i * 4);
            vpre[i] = *(const float4*)(Vt + i * 4);
        }
#pragma unroll
        for (int i = 0; i < 4; i++) {
            *(uint4*)&Ks[klrow * KP + klc0 + 4 * i] = cvt4(kpre[i]);
            *(uint4*)&Vs[klrow * KP + klc0 + 4 * i] = cvt4(vpre[i]);
        }
    }
    __syncthreads();

    float m_i[2], l_i[2];
    float of[8][4];
    m_i[0] = m_i[1] = -1e30f;
    l_i[0] = l_i[1] = 0.0f;
#pragma unroll
    for (int nf = 0; nf < 8; nf++)
#pragma unroll
        for (int r = 0; r < 4; r++) of[nf][r] = 0.0f;

    const int ktmax = 2 * bxr + 1;
    const int qrow = wid * 16 + gid;   // local q rows qrow, qrow+8

    for (int kt = 0; kt <= ktmax; kt++) {
        const int cur = kt & 1;
        uint32_t* Kc = Ks + cur * 64 * KP;
        uint32_t* Vc = Vs + cur * 64 * KP;

        // issue loads for next tile (consumed at bottom of this iteration)
        if (kt < ktmax) {
            const float* Kt = Kb + (size_t)((kt + 1) * 64 + klrow) * 2 * DD;
            const float* Vt = Vb + (size_t)((kt + 1) * 64 + klrow) * 2 * DD;
#pragma unroll
            for (int i = 0; i < 4; i++) {
                kpre[i] = *(const float4*)(Kt + i * 4);
                vpre[i] = *(const float4*)(Vt + i * 4);
            }
        }

        // S = Q @ K^T
        float sf[8][4];
#pragma unroll
        for (int nf = 0; nf < 8; nf++)
#pragma unroll
            for (int r = 0; r < 4; r++) sf[nf][r] = 0.0f;

#pragma unroll
        for (int ks = 0; ks < 8; ks++) {
            const int kb = ks * 8;
            uint32_t af[4];
            af[0] = Qs[(qrow)     * QP + kb + tig];
            af[1] = Qs[(qrow + 8) * QP + kb + tig];
            af[2] = Qs[(qrow)     * QP + kb + tig + 4];
            af[3] = Qs[(qrow + 8) * QP + kb + tig + 4];
#pragma unroll
            for (int nf = 0; nf < 8; nf++) {
                uint32_t bf[2];
                bf[0] = Kc[(nf * 8 + gid) * KP + kb + tig];
                bf[1] = Kc[(nf * 8 + gid) * KP + kb + tig + 4];
                mma_tf32(sf[nf], af, bf);
            }
        }

        // causal mask (only the last two k-tiles can clip)
        if (kt >= ktmax - 1) {
            const int rg0 = q0 + qrow;
#pragma unroll
            for (int nf = 0; nf < 8; nf++) {
                const int cg = kt * 64 + nf * 8 + 2 * tig;
                if (cg     > rg0)     sf[nf][0] = -1e30f;
                if (cg + 1 > rg0)     sf[nf][1] = -1e30f;
                if (cg     > rg0 + 8) sf[nf][2] = -1e30f;
                if (cg + 1 > rg0 + 8) sf[nf][3] = -1e30f;
            }
        }

        // online softmax (rows qrow, qrow+8; 4 lanes of a quad share a row)
#pragma unroll
        for (int r = 0; r < 2; r++) {
            float vmax = -1e30f;
#pragma unroll
            for (int nf = 0; nf < 8; nf++)
                vmax = fmaxf(vmax, fmaxf(sf[nf][2 * r], sf[nf][2 * r + 1]));
            vmax = fmaxf(vmax, __shfl_xor_sync(0xffffffffu, vmax, 1));
            vmax = fmaxf(vmax, __shfl_xor_sync(0xffffffffu, vmax, 2));
            const float mn = fmaxf(m_i[r], vmax);
            const float corr = __expf(m_i[r] - mn);
            float rsum = 0.0f;
#pragma unroll
            for (int nf = 0; nf < 8; nf++) {
                float p0 = __expf(sf[nf][2 * r]     - mn);
                float p1 = __expf(sf[nf][2 * r + 1] - mn);
                sf[nf][2 * r]     = p0;
                sf[nf][2 * r + 1] = p1;
                rsum += p0 + p1;
            }
            rsum += __shfl_xor_sync(0xffffffffu, rsum, 1);
            rsum += __shfl_xor_sync(0xffffffffu, rsum, 2);
            l_i[r] = l_i[r] * corr + rsum;
            m_i[r] = mn;
#pragma unroll
            for (int nf = 0; nf < 8; nf++) {
                of[nf][2 * r]     *= corr;
                of[nf][2 * r + 1] *= corr;
            }
        }

        // stage P (rows are warp-private -> syncwarp suffices)
#pragma unroll
        for (int nf = 0; nf < 8; nf++) {
            const int cc = nf * 8 + 2 * tig;
            uint2 p01 = make_uint2(f2tf32(sf[nf][0]), f2tf32(sf[nf][1]));
            uint2 p23 = make_uint2(f2tf32(sf[nf][2]), f2tf32(sf[nf][3]));
            *(uint2*)&Ps[(qrow)     * QP + cc] = p01;
            *(uint2*)&Ps[(qrow + 8) * QP + cc] = p23;
        }
        __syncwarp();

        // O += P @ V
#pragma unroll
        for (int ks = 0; ks < 8; ks++) {
            const int kb = ks * 8;
            uint32_t af[4];
            af[0] = Ps[(qrow)     * QP + kb + tig];
            af[1] = Ps[(qrow + 8) * QP + kb + tig];
            af[2] = Ps[(qrow)     * QP + kb + tig + 4];
            af[3] = Ps[(qrow + 8) * QP + kb + tig + 4];
#pragma unroll
            for (int nf = 0; nf < 8; nf++) {
                uint32_t bf[2];
                bf[0] = Vc[(kb + tig)     * KP + nf * 8 + gid];
                bf[1] = Vc[(kb + tig + 4) * KP + nf * 8 + gid];
                mma_tf32(of[nf], af, bf);
            }
        }

        // store prefetched next tile into the other buffer
        if (kt < ktmax) {
            uint32_t* Kn = Ks + (1 - cur) * 64 * KP;
            uint32_t* Vn = Vs + (1 - cur) * 64 * KP;
#pragma unroll
            for (int i = 0; i < 4; i++) {
                *(uint4*)&Kn[klrow * KP + klc0 + 4 * i] = cvt4(kpre[i]);
                *(uint4*)&Vn[klrow * KP + klc0 + 4 * i] = cvt4(vpre[i]);
            }
        }
        __syncthreads();
    }

    // epilogue: normalize + merged-head write O[b][q][h*64+d]
    const float inv0 = 1.0f / l_i[0];
    const float inv1 = 1.0f / l_i[1];
    const size_t base0 = ((size_t)b * SS + q0 + qrow)     * DD + h * HDIM;
    const size_t base1 = ((size_t)b * SS + q0 + qrow + 8) * DD + h * HDIM;
#pragma unroll
    for (int nf = 0; nf < 8; nf++) {
        const int cc = nf * 8 + 2 * tig;
        *(float2*)&O[base0 + cc] = make_float2(of[nf][0] * inv0, of[nf][1] * inv0);
        *(float2*)&O[base1 + cc] = make_float2(of[nf][2] * inv1, of[nf][3] * inv1);
    }
}

// ---------------------------------------------------------------------------
// Launch
// ---------------------------------------------------------------------------
extern "C" void kernel_launch(void* const* d_in, const int* in_sizes, int n_in,
                              void* d_out, int out_size)
{
    const float* qf  = (const float*)d_in[0];
    const float* kvf = (const float*)d_in[1];
    // d_in[2] = mask: deterministically causal tril -> handled analytically
    const float* Wq  = (const float*)d_in[3];
    const float* bq  = (const float*)d_in[4];
    const float* Wkv = (const float*)d_in[5];
    const float* bkv = (const float*)d_in[6];
    const float* Wp  = (const float*)d_in[7];
    const float* bp  = (const float*)d_in[8];
    float* out = (float*)d_out;

    float *pQ, *pKV, *pAO;
    cudaGetSymbolAddress((void**)&pQ,  g_Q);
    cudaGetSymbolAddress((void**)&pKV, g_KV);
    cudaGetSymbolAddress((void**)&pAO, g_AO);

    const int M = BB * SS;  // 4096

    // 1) Q projection: (4096 x 1024)
    gemm_tf32_kernel<<<dim3(DD / 128, M / 128), 256>>>(qf, Wq, bq, pQ, M, DD, DD);

    // 2) KV projection: (4096 x 2048)
    gemm_tf32_kernel<<<dim3(2 * DD / 128, M / 128), 256>>>(kvf, Wkv, bkv, pKV, M, 2 * DD, DD);

    // 3) causal attention (tf32 mma, pipelined)
    cudaFuncSetAttribute(attn_tf32_kernel, cudaFuncAttributeMaxDynamicSharedMemorySize, ATTN_SMEM_BYTES);
    attn_tf32_kernel<<<dim3(SS / 128, HH, BB), 256, ATTN_SMEM_BYTES>>>(pQ, pKV, pAO);

    // 4) output projection into d_out
    gemm_tf32_kernel<<<dim3(DD / 128, M / 128), 256>>>(pAO, Wp, bp, out, M, DD, DD);
}